// round 5
// baseline (speedup 1.0000x reference)
#include <cuda_runtime.h>
#include <cuda_fp16.h>
#include <cstdint>

// ---------------------------------------------------------------------------
// TopKRouter via 2-limb fp16 split + mma.sync m16n8k16 (3-product scheme).
// logits = x @ w^T ; softmax ; top-2 (+renorm) ; aux loss.
// x: [T=16384, D=2048] fp32, w: [E=64, D=2048] fp32.
// out (fp32, 4T+1): [indices(2T) | weights(2T) | aux_loss]
// Single fused kernel: inline w split, GEMM, epilogue, last-CTA finalize.
// R5 fix: B-staging stride is 8 B per float4 (4 halves/limb), was 16.
// ---------------------------------------------------------------------------

#define DIM     2048
#define NEXP    64
#define CTAM    112           // tokens per CTA = 7 x m16
#define KC      32            // K per chunk
#define NCHUNK  (DIM / KC)    // 64
#define THREADS 224           // 7 warps
#define MAXCTA  1024

#define PADH    40            // halves per smem row (80 B) -> conflict-free ldmatrix
// per buffer: A0,A1 (112*80=8960 B each), B0,B1 (64*80=5120 B each)
#define SA_OFF(buf, l)  ((buf) * 28160 + (l) * 8960)
#define SB_OFF(buf, l)  ((buf) * 28160 + 17920 + (l) * 5120)
#define SMEM_BYTES      56320

__device__ float g_P[MAXCTA * NEXP];
__device__ int   g_cnt[MAXCTA * NEXP];
__device__ float g_lse2[MAXCTA];
__device__ int   g_ctr;      // zero-init; self-resetting each launch

__device__ __forceinline__ uint32_t smem_u32(const void* p) {
    uint32_t a;
    asm("{ .reg .u64 t; cvta.to.shared.u64 t, %1; cvt.u32.u64 %0, t; }" : "=r"(a) : "l"(p));
    return a;
}
__device__ __forceinline__ void ldsm4(uint32_t* r, uint32_t a) {
    asm volatile("ldmatrix.sync.aligned.m8n8.x4.shared.b16 {%0,%1,%2,%3}, [%4];"
                 : "=r"(r[0]), "=r"(r[1]), "=r"(r[2]), "=r"(r[3]) : "r"(a));
}
__device__ __forceinline__ void mma16816(float* c, const uint32_t* a, uint32_t b0, uint32_t b1) {
    asm volatile("mma.sync.aligned.m16n8k16.row.col.f32.f16.f16.f32 "
                 "{%0,%1,%2,%3},{%4,%5,%6,%7},{%8,%9},{%0,%1,%2,%3};"
                 : "+f"(c[0]), "+f"(c[1]), "+f"(c[2]), "+f"(c[3])
                 : "r"(a[0]), "r"(a[1]), "r"(a[2]), "r"(a[3]), "r"(b0), "r"(b1));
}
// round-nearest 2-limb fp16 split of a float pair -> packed half2 limbs
__device__ __forceinline__ void split2(float f0, float f1, uint32_t& l0, uint32_t& l1) {
    __half2 h0 = __floats2half2_rn(f0, f1);
    float2 g = __half22float2(h0);
    __half2 h1 = __floats2half2_rn(f0 - g.x, f1 - g.y);
    l0 = *(uint32_t*)&h0;
    l1 = *(uint32_t*)&h1;
}

__global__ __launch_bounds__(THREADS, 1)
void router_kernel(const float* __restrict__ x, const float* __restrict__ wgl,
                   float* __restrict__ out, int tokens) {
    extern __shared__ char smem[];
    const uint32_t sb = smem_u32(smem);
    const int tid = threadIdx.x, w = tid >> 5, lane = tid & 31;
    const int cta = blockIdx.x, tok0 = cta * CTAM;
    const int valid = min(CTAM, tokens - tok0);

    __shared__ float sm_m[128];
    __shared__ float sm_is[128];
    __shared__ int   cnt_s[NEXP];
    __shared__ float red_s[4];
    __shared__ int   isLast;

    // ---- GEMM mainloop (double-buffered, 1 sync/chunk) ----
    const float4* xg = (const float4*)(x + (size_t)tok0 * DIM);
    // x staging: 4 float4/thread; idx = i*224+tid: row = idx/8 (112), c4 = idx%8
    int rowx[4], c4x[4];
    float4 xv[4];
#pragma unroll
    for (int i = 0; i < 4; i++) {
        int idx = i * THREADS + tid;
        rowx[i] = idx >> 3; c4x[i] = idx & 7;
        xv[i] = (tok0 + rowx[i] < tokens)
              ? xg[(size_t)rowx[i] * (DIM / 4) + c4x[i]]
              : make_float4(0.f, 0.f, 0.f, 0.f);
    }
    // w staging (tid<128): expert = tid/2, float4 group base = (tid&1)*4
    const int er = tid >> 1, kg4 = (tid & 1) * 4;
    float4 wf[4];
    if (tid < 128) {
#pragma unroll
        for (int i = 0; i < 4; i++)
            wf[i] = ((const float4*)wgl)[(size_t)er * (DIM / 4) + kg4 + i];
    }

    float acc[8][4];
#pragma unroll
    for (int nb = 0; nb < 8; nb++)
#pragma unroll
        for (int j = 0; j < 4; j++) acc[nb][j] = 0.f;

    const uint32_t aRow = (uint32_t)(w * 16 + (lane & 15)) * (PADH * 2) + (lane >> 4) * 16;
    const uint32_t bRow = (uint32_t)((lane & 7) + ((lane >> 4) & 1) * 8) * (PADH * 2)
                        + ((lane >> 3) & 1) * 16;

    for (int c = 0; c < NCHUNK; c++) {
        const int buf = c & 1;
        // store x limbs
#pragma unroll
        for (int i = 0; i < 4; i++) {
            uint32_t p0, p1, q0, q1;
            split2(xv[i].x, xv[i].y, p0, q0);
            split2(xv[i].z, xv[i].w, p1, q1);
            uint32_t off = (uint32_t)rowx[i] * (PADH * 2) + c4x[i] * 8;
            *(uint2*)(smem + SA_OFF(buf, 0) + off) = make_uint2(p0, p1);
            *(uint2*)(smem + SA_OFF(buf, 1) + off) = make_uint2(q0, q1);
        }
        // split + store w limbs (8 bytes of halves per float4 -> stride 8!)
        if (tid < 128) {
#pragma unroll
            for (int i = 0; i < 4; i++) {
                uint32_t p0, p1, q0, q1;
                split2(wf[i].x, wf[i].y, p0, q0);
                split2(wf[i].z, wf[i].w, p1, q1);
                uint32_t off = (uint32_t)er * (PADH * 2) + (kg4 + i) * 8;
                *(uint2*)(smem + SB_OFF(buf, 0) + off) = make_uint2(p0, p1);
                *(uint2*)(smem + SB_OFF(buf, 1) + off) = make_uint2(q0, q1);
            }
        }
        __syncthreads();
        // prefetch next chunk
        if (c + 1 < NCHUNK) {
            int k4 = (c + 1) * (KC / 4);
#pragma unroll
            for (int i = 0; i < 4; i++)
                xv[i] = (tok0 + rowx[i] < tokens)
                      ? xg[(size_t)rowx[i] * (DIM / 4) + k4 + c4x[i]]
                      : make_float4(0.f, 0.f, 0.f, 0.f);
            if (tid < 128) {
#pragma unroll
                for (int i = 0; i < 4; i++)
                    wf[i] = ((const float4*)wgl)[(size_t)er * (DIM / 4) + k4 + kg4 + i];
            }
        }
        // compute: 3 limb products (00, 10, 01); 11 dropped (~6e-9 rel)
        const uint32_t a0b = sb + SA_OFF(buf, 0) + aRow;
        const uint32_t a1b = sb + SA_OFF(buf, 1) + aRow;
        const uint32_t b0b = sb + SB_OFF(buf, 0) + bRow;
        const uint32_t b1b = sb + SB_OFF(buf, 1) + bRow;
#pragma unroll
        for (int ks = 0; ks < 2; ks++) {
            uint32_t af0[4], af1[4];
            ldsm4(af0, a0b + ks * 32);
            ldsm4(af1, a1b + ks * 32);
#pragma unroll
            for (int nb2 = 0; nb2 < 4; nb2++) {       // b limb0: a0*b0 + a1*b0
                uint32_t bf[4];
                ldsm4(bf, b0b + ks * 32 + nb2 * 16 * (PADH * 2));
                mma16816(acc[nb2 * 2    ], af0, bf[0], bf[1]);
                mma16816(acc[nb2 * 2    ], af1, bf[0], bf[1]);
                mma16816(acc[nb2 * 2 + 1], af0, bf[2], bf[3]);
                mma16816(acc[nb2 * 2 + 1], af1, bf[2], bf[3]);
            }
#pragma unroll
            for (int nb2 = 0; nb2 < 4; nb2++) {       // b limb1: a0*b1
                uint32_t bf[4];
                ldsm4(bf, b1b + ks * 32 + nb2 * 16 * (PADH * 2));
                mma16816(acc[nb2 * 2    ], af0, bf[0], bf[1]);
                mma16816(acc[nb2 * 2 + 1], af0, bf[2], bf[3]);
            }
        }
    }
    __syncthreads();   // smem free for logits overlay

    // ---- epilogue: accumulators -> smem logits [112][66] ----
    float* L = (float*)smem;
    {
        int r0 = w * 16 + (lane >> 2);
        int cb = (lane & 3) * 2;
#pragma unroll
        for (int nb = 0; nb < 8; nb++) {
            *(float2*)&L[r0 * 66 + nb * 8 + cb]       = make_float2(acc[nb][0], acc[nb][1]);
            *(float2*)&L[(r0 + 8) * 66 + nb * 8 + cb] = make_float2(acc[nb][2], acc[nb][3]);
        }
    }
    if (tid < NEXP) cnt_s[tid] = 0;
    __syncthreads();

    // ---- pass A: per-token top-2, softmax stats, outputs, z ----
    if (tid < 128) {                 // warps 0-3 fully active (shuffle-safe)
        const int t = tid;
        float z2 = 0.f;
        if (t < valid) {
            const float* Lr = &L[t * 66];
            float v1 = -3.402823466e38f, v2 = -3.402823466e38f;
            int i1 = 0, i2 = 0;
#pragma unroll 8
            for (int e = 0; e < NEXP; e++) {
                float l = Lr[e];
                if (l > v1) { v2 = v1; i2 = i1; v1 = l; i1 = e; }
                else if (l > v2) { v2 = l; i2 = e; }
            }
            float S = 0.f;
#pragma unroll 8
            for (int e = 0; e < NEXP; e++) S += __expf(Lr[e] - v1);
            float invS = 1.f / S;
            sm_m[t] = v1; sm_is[t] = invS;

            float lse = v1 + __logf(S);
            z2 = lse * lse;

            float e2 = __expf(v2 - v1);
            float inv = 1.f / (1.f + e2);
            int gt = tok0 + t;
            out[gt * 2    ] = (float)i1;
            out[gt * 2 + 1] = (float)i2;
            float* wout = out + 2 * tokens;
            wout[gt * 2    ] = inv;
            wout[gt * 2 + 1] = e2 * inv;
            atomicAdd(&cnt_s[i1], 1);
            atomicAdd(&cnt_s[i2], 1);
        }
#pragma unroll
        for (int o = 16; o > 0; o >>= 1) z2 += __shfl_down_sync(0xffffffffu, z2, o);
        if (lane == 0) red_s[tid >> 5] = z2;
    }
    __syncthreads();

    // ---- pass B: per-expert softmax-weight partials (fixed order) ----
    if (tid < NEXP) {
        const int e = tid;
        float P = 0.f;
        for (int t = 0; t < valid; t++)
            P += __expf(L[t * 66 + e] - sm_m[t]) * sm_is[t];
        g_P[cta * NEXP + e]   = P;
        g_cnt[cta * NEXP + e] = cnt_s[e];
    }
    if (tid == 0) g_lse2[cta] = ((red_s[0] + red_s[1]) + red_s[2]) + red_s[3];

    // ---- last CTA finalizes (deterministic fixed-order reduction) ----
    __threadfence();
    __syncthreads();
    if (tid == 0) {
        int prev = atomicAdd(&g_ctr, 1);
        isLast = (prev == (int)gridDim.x - 1);
    }
    __syncthreads();
    if (!isLast) return;

    {
        const int nCta = (int)gridDim.x;
        __shared__ float sP2[3][NEXP];
        __shared__ float sC2[3][NEXP];
        __shared__ float sZ2[160];
        if (tid < 192) {
            int s = tid >> 6, e = tid & 63;
            float P = 0.f, C = 0.f;
            for (int c2 = s; c2 < nCta; c2 += 3) {    // fixed per-slice order
                P += g_P[c2 * NEXP + e];
                C += (float)g_cnt[c2 * NEXP + e];
            }
            sP2[s][e] = P; sC2[s][e] = C;
        }
        if (tid < 160) sZ2[tid] = (tid < nCta) ? g_lse2[tid] : 0.f;
        __syncthreads();
        if (tid == 0) {
            float tsum = 0.f;
            for (int e = 0; e < NEXP; e++) {
                float P = (sP2[0][e] + sP2[1][e]) + sP2[2][e];
                float C = (sC2[0][e] + sC2[1][e]) + sC2[2][e];
                tsum += (C / (float)(tokens * 2)) * (P / (float)tokens);
            }
            float z = 0.f;
            for (int i = 0; i < 160; i++) z += sZ2[i];
            out[4 * tokens] = 0.01f * ((float)NEXP * tsum) + 0.001f * (z / (float)tokens);
            g_ctr = 0;   // self-reset for next launch / graph replay
        }
    }
}

extern "C" void kernel_launch(void* const* d_in, const int* in_sizes, int n_in,
                              void* d_out, int out_size) {
    const float* x = (const float*)d_in[0];
    const float* w = (const float*)d_in[1];
    float* out = (float*)d_out;
    int tokens = in_sizes[0] / DIM;              // 16384
    int nCta   = (tokens + CTAM - 1) / CTAM;     // 147
    cudaFuncSetAttribute(router_kernel, cudaFuncAttributeMaxDynamicSharedMemorySize, SMEM_BYTES);
    router_kernel<<<nCta, THREADS, SMEM_BYTES>>>(x, w, out, tokens);
}

// round 6
// speedup vs baseline: 1.2133x; 1.2133x over previous
#include <cuda_runtime.h>
#include <cuda_fp16.h>
#include <cstdint>

// ---------------------------------------------------------------------------
// TopKRouter via 2-limb fp16 split + mma.sync m16n8k16 (3-product scheme).
// logits = x @ w^T ; softmax ; top-2 (+renorm) ; aux loss.
// x: [T=16384, D=2048] fp32, w: [E=64, D=2048] fp32.
// out (fp32, 4T+1): [indices(2T) | weights(2T) | aux_loss]
// R6: 8 warps, 4x2 warp grid, warp tile M32xN32 -> B-ldsm dup x4 (was x7),
//     CTAM=128 (grid=128, exact), mod-4-balanced warps.
// ---------------------------------------------------------------------------

#define DIM     2048
#define NEXP    64
#define CTAM    128           // tokens per CTA = 8 x m16
#define KC      32            // K per chunk
#define NCHUNK  (DIM / KC)    // 64
#define THREADS 256           // 8 warps
#define MAXCTA  1024

#define PADH    40            // halves per smem row (80 B) -> conflict-free ldmatrix
// per buffer: A0,A1 (128*80=10240 B each), B0,B1 (64*80=5120 B each)
#define SA_OFF(buf, l)  ((buf) * 30720 + (l) * 10240)
#define SB_OFF(buf, l)  ((buf) * 30720 + 20480 + (l) * 5120)
#define SMEM_BYTES      61440

__device__ float g_P[MAXCTA * NEXP];
__device__ int   g_cnt[MAXCTA * NEXP];
__device__ float g_lse2[MAXCTA];
__device__ int   g_ctr;      // zero-init; self-resetting each launch

__device__ __forceinline__ uint32_t smem_u32(const void* p) {
    uint32_t a;
    asm("{ .reg .u64 t; cvta.to.shared.u64 t, %1; cvt.u32.u64 %0, t; }" : "=r"(a) : "l"(p));
    return a;
}
__device__ __forceinline__ void ldsm4(uint32_t* r, uint32_t a) {
    asm volatile("ldmatrix.sync.aligned.m8n8.x4.shared.b16 {%0,%1,%2,%3}, [%4];"
                 : "=r"(r[0]), "=r"(r[1]), "=r"(r[2]), "=r"(r[3]) : "r"(a));
}
__device__ __forceinline__ void mma16816(float* c, const uint32_t* a, uint32_t b0, uint32_t b1) {
    asm volatile("mma.sync.aligned.m16n8k16.row.col.f32.f16.f16.f32 "
                 "{%0,%1,%2,%3},{%4,%5,%6,%7},{%8,%9},{%0,%1,%2,%3};"
                 : "+f"(c[0]), "+f"(c[1]), "+f"(c[2]), "+f"(c[3])
                 : "r"(a[0]), "r"(a[1]), "r"(a[2]), "r"(a[3]), "r"(b0), "r"(b1));
}
// round-nearest 2-limb fp16 split of a float pair -> packed half2 limbs
__device__ __forceinline__ void split2(float f0, float f1, uint32_t& l0, uint32_t& l1) {
    __half2 h0 = __floats2half2_rn(f0, f1);
    float2 g = __half22float2(h0);
    __half2 h1 = __floats2half2_rn(f0 - g.x, f1 - g.y);
    l0 = *(uint32_t*)&h0;
    l1 = *(uint32_t*)&h1;
}

__global__ __launch_bounds__(THREADS, 1)
void router_kernel(const float* __restrict__ x, const float* __restrict__ wgl,
                   float* __restrict__ out, int tokens) {
    extern __shared__ char smem[];
    const uint32_t sb = smem_u32(smem);
    const int tid = threadIdx.x, w = tid >> 5, lane = tid & 31;
    const int cta = blockIdx.x, tok0 = cta * CTAM;
    const int mi = w >> 1, ni = w & 1;     // 4x2 warp grid: M32 x N32 per warp

    __shared__ float sm_m[CTAM];
    __shared__ float sm_is[CTAM];
    __shared__ int   cnt_s[NEXP];
    __shared__ float red_s[4];
    __shared__ int   isLast;

    // ---- GEMM mainloop (double-buffered, 1 sync/chunk) ----
    const float4* xg = (const float4*)(x + (size_t)tok0 * DIM);
    // x staging: 4 float4/thread; idx = i*256+tid: row = idx/8 (128), c4 = idx%8
    int rowx[4], c4x[4];
    float4 xv[4];
#pragma unroll
    for (int i = 0; i < 4; i++) {
        int idx = i * THREADS + tid;
        rowx[i] = idx >> 3; c4x[i] = idx & 7;
        xv[i] = xg[(size_t)rowx[i] * (DIM / 4) + c4x[i]];
    }
    // w staging: 2 float4/thread: expert = tid/4, float4 base = (tid&3)*2
    const int er = tid >> 2, kg4 = (tid & 3) * 2;
    float4 wf[2];
#pragma unroll
    for (int i = 0; i < 2; i++)
        wf[i] = ((const float4*)wgl)[(size_t)er * (DIM / 4) + kg4 + i];

    float acc[2][4][4];                     // [m-tile][n8][frag]
#pragma unroll
    for (int t = 0; t < 2; t++)
#pragma unroll
        for (int nb = 0; nb < 4; nb++)
#pragma unroll
            for (int j = 0; j < 4; j++) acc[t][nb][j] = 0.f;

    // ldmatrix lane address components (byte offsets within a tile)
    const uint32_t aOff = (uint32_t)(mi * 32 + (lane & 15)) * (PADH * 2) + (lane >> 4) * 16;
    const uint32_t bOff = (uint32_t)(ni * 32 + (lane & 7) + ((lane >> 4) & 1) * 8) * (PADH * 2)
                        + ((lane >> 3) & 1) * 16;

    for (int c = 0; c < NCHUNK; c++) {
        const int buf = c & 1;
        // store x limbs
#pragma unroll
        for (int i = 0; i < 4; i++) {
            uint32_t p0, p1, q0, q1;
            split2(xv[i].x, xv[i].y, p0, q0);
            split2(xv[i].z, xv[i].w, p1, q1);
            uint32_t off = (uint32_t)rowx[i] * (PADH * 2) + c4x[i] * 8;
            *(uint2*)(smem + SA_OFF(buf, 0) + off) = make_uint2(p0, p1);
            *(uint2*)(smem + SA_OFF(buf, 1) + off) = make_uint2(q0, q1);
        }
        // split + store w limbs (8 bytes of halves per float4)
#pragma unroll
        for (int i = 0; i < 2; i++) {
            uint32_t p0, p1, q0, q1;
            split2(wf[i].x, wf[i].y, p0, q0);
            split2(wf[i].z, wf[i].w, p1, q1);
            uint32_t off = (uint32_t)er * (PADH * 2) + (kg4 + i) * 8;
            *(uint2*)(smem + SB_OFF(buf, 0) + off) = make_uint2(p0, p1);
            *(uint2*)(smem + SB_OFF(buf, 1) + off) = make_uint2(q0, q1);
        }
        __syncthreads();
        // prefetch next chunk
        if (c + 1 < NCHUNK) {
            int k4 = (c + 1) * (KC / 4);
#pragma unroll
            for (int i = 0; i < 4; i++)
                xv[i] = xg[(size_t)rowx[i] * (DIM / 4) + k4 + c4x[i]];
#pragma unroll
            for (int i = 0; i < 2; i++)
                wf[i] = ((const float4*)wgl)[(size_t)er * (DIM / 4) + k4 + kg4 + i];
        }
        // compute: 3 limb products (00, 10, 01); 11 dropped (~6e-9 rel)
        const uint32_t a0b = sb + SA_OFF(buf, 0) + aOff;
        const uint32_t a1b = sb + SA_OFF(buf, 1) + aOff;
        const uint32_t b0b = sb + SB_OFF(buf, 0) + bOff;
        const uint32_t b1b = sb + SB_OFF(buf, 1) + bOff;
#pragma unroll
        for (int ks = 0; ks < 2; ks++) {
            uint32_t af0[2][4], af1[2][4];
#pragma unroll
            for (int t = 0; t < 2; t++) {
                ldsm4(af0[t], a0b + t * 16 * (PADH * 2) + ks * 32);
                ldsm4(af1[t], a1b + t * 16 * (PADH * 2) + ks * 32);
            }
#pragma unroll
            for (int nb2 = 0; nb2 < 2; nb2++) {
                uint32_t bf[4];
                ldsm4(bf, b0b + nb2 * 16 * (PADH * 2) + ks * 32);   // b limb0
#pragma unroll
                for (int t = 0; t < 2; t++) {
                    mma16816(acc[t][nb2 * 2    ], af0[t], bf[0], bf[1]);
                    mma16816(acc[t][nb2 * 2    ], af1[t], bf[0], bf[1]);
                    mma16816(acc[t][nb2 * 2 + 1], af0[t], bf[2], bf[3]);
                    mma16816(acc[t][nb2 * 2 + 1], af1[t], bf[2], bf[3]);
                }
                ldsm4(bf, b1b + nb2 * 16 * (PADH * 2) + ks * 32);   // b limb1
#pragma unroll
                for (int t = 0; t < 2; t++) {
                    mma16816(acc[t][nb2 * 2    ], af0[t], bf[0], bf[1]);
                    mma16816(acc[t][nb2 * 2 + 1], af0[t], bf[2], bf[3]);
                }
            }
        }
    }
    __syncthreads();   // smem free for logits overlay

    // ---- epilogue: accumulators -> smem logits [128][66] ----
    float* L = (float*)smem;
    {
        int cb = ni * 32 + (lane & 3) * 2;
#pragma unroll
        for (int t = 0; t < 2; t++) {
            int r0 = mi * 32 + t * 16 + (lane >> 2);
#pragma unroll
            for (int nb = 0; nb < 4; nb++) {
                *(float2*)&L[r0 * 66 + cb + nb * 8]       = make_float2(acc[t][nb][0], acc[t][nb][1]);
                *(float2*)&L[(r0 + 8) * 66 + cb + nb * 8] = make_float2(acc[t][nb][2], acc[t][nb][3]);
            }
        }
    }
    if (tid < NEXP) cnt_s[tid] = 0;
    __syncthreads();

    // ---- pass A: per-token top-2, softmax stats, outputs, z ----
    if (tid < CTAM) {
        const int t = tid;
        const float* Lr = &L[t * 66];
        float v1 = -3.402823466e38f, v2 = -3.402823466e38f;
        int i1 = 0, i2 = 0;
#pragma unroll 8
        for (int e = 0; e < NEXP; e++) {
            float l = Lr[e];
            if (l > v1) { v2 = v1; i2 = i1; v1 = l; i1 = e; }
            else if (l > v2) { v2 = l; i2 = e; }
        }
        float S = 0.f;
#pragma unroll 8
        for (int e = 0; e < NEXP; e++) S += __expf(Lr[e] - v1);
        float invS = 1.f / S;
        sm_m[t] = v1; sm_is[t] = invS;

        float lse = v1 + __logf(S);
        float z2 = lse * lse;
#pragma unroll
        for (int o = 16; o > 0; o >>= 1) z2 += __shfl_down_sync(0xffffffffu, z2, o);
        if (lane == 0) red_s[t >> 5] = z2;

        float e2 = __expf(v2 - v1);
        float inv = 1.f / (1.f + e2);
        int gt = tok0 + t;
        out[gt * 2    ] = (float)i1;
        out[gt * 2 + 1] = (float)i2;
        float* wout = out + 2 * tokens;
        wout[gt * 2    ] = inv;
        wout[gt * 2 + 1] = e2 * inv;
        atomicAdd(&cnt_s[i1], 1);
        atomicAdd(&cnt_s[i2], 1);
    }
    __syncthreads();

    // ---- pass B: per-expert softmax-weight partials (fixed order) ----
    if (tid < NEXP) {
        const int e = tid;
        float P = 0.f;
#pragma unroll 8
        for (int t = 0; t < CTAM; t++)
            P += __expf(L[t * 66 + e] - sm_m[t]) * sm_is[t];
        g_P[cta * NEXP + e]   = P;
        g_cnt[cta * NEXP + e] = cnt_s[e];
    }
    if (tid == 0) g_lse2[cta] = ((red_s[0] + red_s[1]) + red_s[2]) + red_s[3];

    // ---- last CTA finalizes (deterministic fixed-order reduction) ----
    __threadfence();
    __syncthreads();
    if (tid == 0) {
        int prev = atomicAdd(&g_ctr, 1);
        isLast = (prev == (int)gridDim.x - 1);
    }
    __syncthreads();
    if (!isLast) return;

    {
        const int nCta = (int)gridDim.x;
        __shared__ float sP2[2][NEXP];
        __shared__ float sC2[2][NEXP];
        __shared__ float sZ2[MAXCTA / 4];
        if (tid < 128) {
            int s = tid >> 6, e = tid & 63;
            float P = 0.f, C = 0.f;
            for (int c2 = s; c2 < nCta; c2 += 2) {    // fixed per-slice order
                P += g_P[c2 * NEXP + e];
                C += (float)g_cnt[c2 * NEXP + e];
            }
            sP2[s][e] = P; sC2[s][e] = C;
        }
        if (tid < 256) sZ2[tid] = (tid < nCta) ? g_lse2[tid] : 0.f;
        __syncthreads();
        if (tid == 0) {
            float tsum = 0.f;
            for (int e = 0; e < NEXP; e++) {
                float P = sP2[0][e] + sP2[1][e];
                float C = sC2[0][e] + sC2[1][e];
                tsum += (C / (float)(tokens * 2)) * (P / (float)tokens);
            }
            float z = 0.f;
            for (int i = 0; i < 256; i++) z += sZ2[i];
            out[4 * tokens] = 0.01f * ((float)NEXP * tsum) + 0.001f * (z / (float)tokens);
            g_ctr = 0;   // self-reset for next launch / graph replay
        }
    }
}

extern "C" void kernel_launch(void* const* d_in, const int* in_sizes, int n_in,
                              void* d_out, int out_size) {
    const float* x = (const float*)d_in[0];
    const float* w = (const float*)d_in[1];
    float* out = (float*)d_out;
    int tokens = in_sizes[0] / DIM;              // 16384
    int nCta   = tokens / CTAM;                  // 128 (exact)
    cudaFuncSetAttribute(router_kernel, cudaFuncAttributeMaxDynamicSharedMemorySize, SMEM_BYTES);
    router_kernel<<<nCta, THREADS, SMEM_BYTES>>>(x, w, out, tokens);
}